// round 3
// baseline (speedup 1.0000x reference)
#include <cuda_runtime.h>
#include <cstdint>

#define TT   28      // timesteps
#define IND  28      // input features (layer 0)
#define HID  64      // hidden
#define GG   256     // 4*HID gate rows
#define EE   16      // batch elements per CTA
#define ES   20      // padded row stride for hs/h1seq (16 data + 4 pad), 80B = 16B-aligned rows
#define AS   (GG+8)  // act row stride
#define OUTD 10

// Shared memory layout (floats), all offsets 16B aligned:
//  h1seq [TT][HID][ES]  = 35840
//  xbuf  [2][IND][EE]   =   896
//  hs    [HID][ES]      =  1280
//  act   [EE][AS]       =  4224
//  wlin  [OUTD*HID]     =   640
//  blin  [16]           =    16
#define OFF_H1SEQ 0
#define OFF_XBUF  (OFF_H1SEQ + TT*HID*ES)
#define OFF_HS    (OFF_XBUF + 2*IND*EE)
#define OFF_ACT   (OFF_HS + HID*ES)
#define OFF_WLIN  (OFF_ACT + EE*AS)
#define OFF_BLIN  (OFF_WLIN + OUTD*HID)
#define SMEM_FLOATS (OFF_BLIN + 16)
#define SMEM_BYTES  (SMEM_FLOATS * 4)

typedef unsigned long long u64;

__device__ __forceinline__ u64 splat2(float w) {
    u64 r; asm("mov.b64 %0, {%1, %1};" : "=l"(r) : "f"(w)); return r;
}
__device__ __forceinline__ void ffma2(u64& d, u64 a, u64 b) {
    asm("fma.rn.f32x2 %0, %1, %2, %0;" : "+l"(d) : "l"(a), "l"(b));
}
__device__ __forceinline__ float2 unpack2(u64 v) {
    float2 f; asm("mov.b64 {%0, %1}, %2;" : "=f"(f.x), "=f"(f.y) : "l"(v)); return f;
}

__device__ __forceinline__ float fsig(float x) {
    x = fminf(fmaxf(x, -30.0f), 30.0f);
    return __fdividef(1.0f, 1.0f + __expf(-x));
}
__device__ __forceinline__ float ftanh(float x) {
    x = fminf(fmaxf(x, -15.0f), 15.0f);
    float e = __expf(2.0f * x);
    return __fdividef(e - 1.0f, e + 1.0f);
}

// accumulate 16 batch elements (8 f32x2 pairs) from a 16-float row at `ptr`
#define GACC(accs, ptr, pw) do {                                             \
    const ulonglong2* _p = reinterpret_cast<const ulonglong2*>(ptr);         \
    ulonglong2 _q0 = _p[0], _q1 = _p[1], _q2 = _p[2], _q3 = _p[3];           \
    ffma2((accs)[0], _q0.x, (pw)); ffma2((accs)[1], _q0.y, (pw));            \
    ffma2((accs)[2], _q1.x, (pw)); ffma2((accs)[3], _q1.y, (pw));            \
    ffma2((accs)[4], _q2.x, (pw)); ffma2((accs)[5], _q2.y, (pw));            \
    ffma2((accs)[6], _q3.x, (pw)); ffma2((accs)[7], _q3.y, (pw));            \
} while (0)

__global__ void __launch_bounds__(256, 1)
rnn_fused_kernel(const float* __restrict__ x,
                 const float* __restrict__ Wih0, const float* __restrict__ Whh0,
                 const float* __restrict__ bih0, const float* __restrict__ bhh0,
                 const float* __restrict__ Wih1, const float* __restrict__ Whh1,
                 const float* __restrict__ bih1, const float* __restrict__ bhh1,
                 const float* __restrict__ Wlin, const float* __restrict__ blin,
                 float* __restrict__ out)
{
    extern __shared__ float sm[];
    float* h1seq = sm + OFF_H1SEQ;
    float* xbuf  = sm + OFF_XBUF;
    float* hs    = sm + OFF_HS;
    float* act   = sm + OFF_ACT;
    float* wlin  = sm + OFF_WLIN;
    float* blin_s= sm + OFF_BLIN;

    const int j  = threadIdx.x;             // gate row 0..255
    const int e0 = blockIdx.x * EE;
    const int unit = j & 63;
    const int eb   = (j >> 6) << 2;         // 4 batch elems per thread in update
    const int gt   = j >> 6;                // gate type: 0:i 1:f 2:g 3:o

    // init: zero hs, stage xbuf[0], load linear head
    for (int idx = j; idx < HID * ES; idx += 256) hs[idx] = 0.0f;
    for (int idx = j; idx < IND * EE; idx += 256) {
        int e = idx & (EE - 1), k = idx >> 4;
        xbuf[k * EE + e] = x[(size_t)(e0 + e) * (TT * IND) + 0 * IND + k];
    }
    for (int idx = j; idx < OUTD * HID; idx += 256) wlin[idx] = Wlin[idx];
    if (j < OUTD) blin_s[j] = blin[j];

    float c[4];
#pragma unroll
    for (int q = 0; q < 4; q++) c[q] = 0.0f;

    // ================= Layer 0 =================
    {
        float wi[IND], wh[HID];
#pragma unroll
        for (int k = 0; k < IND; k++) wi[k] = Wih0[j * IND + k];
#pragma unroll
        for (int k = 0; k < HID; k++) wh[k] = Whh0[j * HID + k];
        const u64 pbias = splat2(bih0[j] + bhh0[j]);

        __syncthreads();

#pragma unroll 1
        for (int t = 0; t < TT; t++) {
            const float* xb = xbuf + (t & 1) * (IND * EE);

            u64 acc[8];
#pragma unroll
            for (int i = 0; i < 8; i++) acc[i] = pbias;

#pragma unroll
            for (int k = 0; k < IND; k++) {
                u64 pw = splat2(wi[k]);
                GACC(acc, xb + k * EE, pw);
            }
#pragma unroll
            for (int k = 0; k < HID; k++) {
                u64 pw = splat2(wh[k]);
                GACC(acc, hs + k * ES, pw);
            }

#pragma unroll
            for (int i = 0; i < 8; i++) {
                float2 v = unpack2(acc[i]);
                float a0 = (gt == 2) ? ftanh(v.x) : fsig(v.x);
                float a1 = (gt == 2) ? ftanh(v.y) : fsig(v.y);
                act[(2 * i) * AS + j]     = a0;
                act[(2 * i + 1) * AS + j] = a1;
            }
            __syncthreads();

            // distributed cell update: all 256 threads, 4 cells each
            float* h1t = h1seq + t * HID * ES;
#pragma unroll
            for (int q = 0; q < 4; q++) {
                int e = eb + q;
                const float* ae = act + e * AS;
                float ig = ae[unit];
                float fg = ae[64 + unit];
                float gg = ae[128 + unit];
                float og = ae[192 + unit];
                c[q] = fg * c[q] + ig * gg;
                float h = og * ftanh(c[q]);
                hs[unit * ES + e] = h;
                h1t[unit * ES + e] = h;
            }
            // stage x for t+1 (double buffer)
            if (t + 1 < TT) {
                float* xn = xbuf + ((t + 1) & 1) * (IND * EE);
                for (int idx = j; idx < IND * EE; idx += 256) {
                    int e = idx & (EE - 1), k = idx >> 4;
                    xn[k * EE + e] = x[(size_t)(e0 + e) * (TT * IND) + (t + 1) * IND + k];
                }
            }
            __syncthreads();
        }
    }

    // reset state for layer 1
#pragma unroll
    for (int q = 0; q < 4; q++) c[q] = 0.0f;
    for (int idx = j; idx < HID * ES; idx += 256) hs[idx] = 0.0f;

    // ================= Layer 1 =================
    {
        float wi[HID], wh[HID];
#pragma unroll
        for (int k = 0; k < HID; k++) wi[k] = Wih1[j * HID + k];
#pragma unroll
        for (int k = 0; k < HID; k++) wh[k] = Whh1[j * HID + k];
        const u64 pbias = splat2(bih1[j] + bhh1[j]);

        __syncthreads();

#pragma unroll 1
        for (int t = 0; t < TT; t++) {
            const float* h1t = h1seq + t * HID * ES;

            u64 acc[8];
#pragma unroll
            for (int i = 0; i < 8; i++) acc[i] = pbias;

#pragma unroll
            for (int k = 0; k < HID; k++) {
                u64 pa = splat2(wi[k]);
                u64 pb = splat2(wh[k]);
                GACC(acc, h1t + k * ES, pa);
                GACC(acc, hs + k * ES, pb);
            }

#pragma unroll
            for (int i = 0; i < 8; i++) {
                float2 v = unpack2(acc[i]);
                float a0 = (gt == 2) ? ftanh(v.x) : fsig(v.x);
                float a1 = (gt == 2) ? ftanh(v.y) : fsig(v.y);
                act[(2 * i) * AS + j]     = a0;
                act[(2 * i + 1) * AS + j] = a1;
            }
            __syncthreads();

#pragma unroll
            for (int q = 0; q < 4; q++) {
                int e = eb + q;
                const float* ae = act + e * AS;
                float ig = ae[unit];
                float fg = ae[64 + unit];
                float gg = ae[128 + unit];
                float og = ae[192 + unit];
                c[q] = fg * c[q] + ig * gg;
                float h = og * ftanh(c[q]);
                hs[unit * ES + e] = h;
            }
            __syncthreads();
        }
    }

    // ================= Linear head =================
    // hs holds h2[T-1] as [unit][e] (stride ES)
    if (j < OUTD * EE) {
        int e = j & (EE - 1);
        int o = j >> 4;
        float s = blin_s[o];
#pragma unroll
        for (int k = 0; k < HID; k++)
            s += wlin[o * HID + k] * hs[k * ES + e];
        out[(size_t)(e0 + e) * OUTD + o] = s;
    }
}

extern "C" void kernel_launch(void* const* d_in, const int* in_sizes, int n_in,
                              void* d_out, int out_size)
{
    const float* x    = (const float*)d_in[0];
    const float* Wih0 = (const float*)d_in[1];
    const float* Whh0 = (const float*)d_in[2];
    const float* bih0 = (const float*)d_in[3];
    const float* bhh0 = (const float*)d_in[4];
    const float* Wih1 = (const float*)d_in[5];
    const float* Whh1 = (const float*)d_in[6];
    const float* bih1 = (const float*)d_in[7];
    const float* bhh1 = (const float*)d_in[8];
    const float* Wlin = (const float*)d_in[9];
    const float* blin = (const float*)d_in[10];
    float* out = (float*)d_out;

    int B = in_sizes[0] / (TT * IND);   // 16384
    int grid = B / EE;                  // 1024

    cudaFuncSetAttribute(rnn_fused_kernel,
                         cudaFuncAttributeMaxDynamicSharedMemorySize, SMEM_BYTES);
    rnn_fused_kernel<<<grid, 256, SMEM_BYTES>>>(
        x, Wih0, Whh0, bih0, bhh0, Wih1, Whh1, bih1, bhh1, Wlin, blin, out);
}

// round 4
// speedup vs baseline: 1.0811x; 1.0811x over previous
#include <cuda_runtime.h>
#include <cstdint>

#define TT   28
#define IND  28
#define HID  64
#define GG   256
#define EE   16
#define ES   20        // padded row stride (floats): 80B, 16B-aligned
#define AS   (GG+8)
#define OUTD 10
#define NT   512       // threads per CTA
#define KH0  46        // per-half K for layer 0 (28 x + 64 h = 92)
#define XROW 257       // u64 stride for exchange rows

// Shared memory layout (floats):
//  h1seq [TT][HID][ES]        = 35840
//  zbuf: xcur[IND][ES] + hs[HID][ES] contiguous = 92*20 = 1840
//  act   [EE][AS]             = 4224
//  xch   8 rows * XROW u64    = 4112 floats
//  wlin  [OUTD*HID] = 640, blin 16
#define OFF_H1SEQ 0
#define OFF_ZBUF  (OFF_H1SEQ + TT*HID*ES)
#define OFF_HS    (OFF_ZBUF + IND*ES)
#define OFF_ACT   (OFF_ZBUF + (IND+HID)*ES)
#define OFF_XCH   (OFF_ACT + EE*AS)
#define OFF_WLIN  (OFF_XCH + 8*XROW*2)
#define OFF_BLIN  (OFF_WLIN + OUTD*HID)
#define SMEM_FLOATS (OFF_BLIN + 16)
#define SMEM_BYTES  (SMEM_FLOATS * 4)

typedef unsigned long long u64;

__device__ __forceinline__ u64 splat2(float w) {
    u64 r; asm("mov.b64 %0, {%1, %1};" : "=l"(r) : "f"(w)); return r;
}
__device__ __forceinline__ void ffma2(u64& d, u64 a, u64 b) {
    asm("fma.rn.f32x2 %0, %1, %2, %0;" : "+l"(d) : "l"(a), "l"(b));
}
__device__ __forceinline__ void fadd2(u64& d, u64 a) {
    asm("add.rn.f32x2 %0, %1, %0;" : "+l"(d) : "l"(a));
}
__device__ __forceinline__ float2 unpack2(u64 v) {
    float2 f; asm("mov.b64 {%0, %1}, %2;" : "=f"(f.x), "=f"(f.y) : "l"(v)); return f;
}

__device__ __forceinline__ float fsig(float x) {
    x = fminf(fmaxf(x, -30.0f), 30.0f);
    return __fdividef(1.0f, 1.0f + __expf(-x));
}
__device__ __forceinline__ float ftanh(float x) {
    x = fminf(fmaxf(x, -15.0f), 15.0f);
    float e = __expf(2.0f * x);
    return __fdividef(e - 1.0f, e + 1.0f);
}

// accumulate 16 batch elems (8 f32x2 pairs) from a 16-float row at `ptr`
#define GACC(accs, ptr, pw) do {                                             \
    const ulonglong2* _p = reinterpret_cast<const ulonglong2*>(ptr);         \
    ulonglong2 _q0 = _p[0], _q1 = _p[1], _q2 = _p[2], _q3 = _p[3];           \
    ffma2((accs)[0], _q0.x, (pw)); ffma2((accs)[1], _q0.y, (pw));            \
    ffma2((accs)[2], _q1.x, (pw)); ffma2((accs)[3], _q1.y, (pw));            \
    ffma2((accs)[4], _q2.x, (pw)); ffma2((accs)[5], _q2.y, (pw));            \
    ffma2((accs)[6], _q3.x, (pw)); ffma2((accs)[7], _q3.y, (pw));            \
} while (0)

__global__ void __launch_bounds__(NT, 1)
rnn_fused_kernel(const float* __restrict__ x,
                 const float* __restrict__ Wih0, const float* __restrict__ Whh0,
                 const float* __restrict__ bih0, const float* __restrict__ bhh0,
                 const float* __restrict__ Wih1, const float* __restrict__ Whh1,
                 const float* __restrict__ bih1, const float* __restrict__ bhh1,
                 const float* __restrict__ Wlin, const float* __restrict__ blin,
                 float* __restrict__ out)
{
    extern __shared__ float sm[];
    float* h1seq = sm + OFF_H1SEQ;
    float* zbuf  = sm + OFF_ZBUF;          // xcur rows [0,28) + hs rows [28,92)
    float* hs    = sm + OFF_HS;
    float* act   = sm + OFF_ACT;
    u64*   xch   = reinterpret_cast<u64*>(sm + OFF_XCH);
    float* wlin  = sm + OFF_WLIN;
    float* blin_s= sm + OFF_BLIN;

    const int tid  = threadIdx.x;
    const int j    = tid & 255;            // gate row
    const int half = tid >> 8;             // K-split half
    const int gt   = j >> 6;               // 0:i 1:f 2:g 3:o
    const int e0   = blockIdx.x * EE;
    const int unit = tid & 63;             // cell update mapping
    const int eu   = tid >> 6;             // e' in [0,8): handles e' and e'+8

    // init: zero hs, stage x(t=0), load head weights
    for (int idx = tid; idx < HID * ES; idx += NT) hs[idx] = 0.0f;
    {
        int e = tid >> 5, k = tid & 31;
        if (e < EE && k < IND)
            zbuf[k * ES + e] = x[(size_t)(e0 + e) * (TT * IND) + k];
    }
    for (int idx = tid; idx < OUTD * HID; idx += NT) wlin[idx] = Wlin[idx];
    if (tid < OUTD) blin_s[tid] = blin[tid];

    float c[2];
    c[0] = 0.0f; c[1] = 0.0f;

    // ================= Layer 0 =================
    {
        // combined operand rows r in [0,92): r<28 -> x weights, else h weights
        float wv[KH0];
#pragma unroll
        for (int i = 0; i < KH0; i++) {
            int r = half * KH0 + i;
            wv[i] = (r < IND) ? Wih0[j * IND + r] : Whh0[j * HID + (r - IND)];
        }
        const u64 pbias = half ? 0ULL : splat2(bih0[j] + bhh0[j]);
        const float* zbase = zbuf + half * KH0 * ES;

        __syncthreads();

#pragma unroll 1
        for (int t = 0; t < TT; t++) {
            u64 acc[8];
#pragma unroll
            for (int i = 0; i < 8; i++) acc[i] = pbias;

#pragma unroll
            for (int k = 0; k < KH0; k++) {
                u64 pw = splat2(wv[k]);
                GACC(acc, zbase + k * ES, pw);
            }

            // exchange: half0 ships e8-15 (acc[4..7]) in rows 0-3,
            //           half1 ships e0-7  (acc[0..3]) in rows 4-7
#pragma unroll
            for (int q = 0; q < 4; q++)
                xch[(half ? (4 + q) : q) * XROW + j] = acc[half ? q : (4 + q)];
            __syncthreads();

            // combine + activate own e-slice
#pragma unroll
            for (int q = 0; q < 4; q++) {
                u64 mine = half ? acc[4 + q] : acc[q];
                fadd2(mine, xch[(half ? q : (4 + q)) * XROW + j]);
                float2 v = unpack2(mine);
                int e = half * 8 + 2 * q;
                float a0 = (gt == 2) ? ftanh(v.x) : fsig(v.x);
                float a1 = (gt == 2) ? ftanh(v.y) : fsig(v.y);
                act[e * AS + j]       = a0;
                act[(e + 1) * AS + j] = a1;
            }
            __syncthreads();

            // distributed cell update: 512 threads, 2 cells each
            float* h1t = h1seq + t * HID * ES;
#pragma unroll
            for (int q = 0; q < 2; q++) {
                int e = eu + q * 8;
                const float* ae = act + e * AS;
                float ig = ae[unit];
                float fg = ae[64 + unit];
                float gg = ae[128 + unit];
                float og = ae[192 + unit];
                c[q] = fg * c[q] + ig * gg;
                float h = og * ftanh(c[q]);
                hs[unit * ES + e] = h;
                h1t[unit * ES + e] = h;
            }
            // stage x for t+1 (safe: consumers read before B1 of next iter)
            if (t + 1 < TT) {
                int e = tid >> 5, k = tid & 31;
                if (e < EE && k < IND)
                    zbuf[k * ES + e] =
                        x[(size_t)(e0 + e) * (TT * IND) + (t + 1) * IND + k];
            }
            __syncthreads();
        }
    }

    // reset state for layer 1
    c[0] = 0.0f; c[1] = 0.0f;
    for (int idx = tid; idx < HID * ES; idx += NT) hs[idx] = 0.0f;

    // ================= Layer 1 =================
    {
        // half0: input weights (operand h1seq[t]); half1: recurrent (operand hs)
        float wv[HID];
        const float* Wsel = half ? Whh1 : Wih1;
#pragma unroll
        for (int k = 0; k < HID; k++) wv[k] = Wsel[j * HID + k];
        const u64 pbias = half ? 0ULL : splat2(bih1[j] + bhh1[j]);

        __syncthreads();

#pragma unroll 1
        for (int t = 0; t < TT; t++) {
            const float* base = half ? hs : (h1seq + t * HID * ES);

            u64 acc[8];
#pragma unroll
            for (int i = 0; i < 8; i++) acc[i] = pbias;

#pragma unroll
            for (int k = 0; k < HID; k++) {
                u64 pw = splat2(wv[k]);
                GACC(acc, base + k * ES, pw);
            }

#pragma unroll
            for (int q = 0; q < 4; q++)
                xch[(half ? (4 + q) : q) * XROW + j] = acc[half ? q : (4 + q)];
            __syncthreads();

#pragma unroll
            for (int q = 0; q < 4; q++) {
                u64 mine = half ? acc[4 + q] : acc[q];
                fadd2(mine, xch[(half ? q : (4 + q)) * XROW + j]);
                float2 v = unpack2(mine);
                int e = half * 8 + 2 * q;
                float a0 = (gt == 2) ? ftanh(v.x) : fsig(v.x);
                float a1 = (gt == 2) ? ftanh(v.y) : fsig(v.y);
                act[e * AS + j]       = a0;
                act[(e + 1) * AS + j] = a1;
            }
            __syncthreads();

#pragma unroll
            for (int q = 0; q < 2; q++) {
                int e = eu + q * 8;
                const float* ae = act + e * AS;
                float ig = ae[unit];
                float fg = ae[64 + unit];
                float gg = ae[128 + unit];
                float og = ae[192 + unit];
                c[q] = fg * c[q] + ig * gg;
                float h = og * ftanh(c[q]);
                hs[unit * ES + e] = h;
            }
            __syncthreads();
        }
    }

    // ================= Linear head =================
    if (tid < OUTD * EE) {
        int e = tid & (EE - 1);
        int o = tid >> 4;
        float s = blin_s[o];
#pragma unroll
        for (int k = 0; k < HID; k++)
            s += wlin[o * HID + k] * hs[k * ES + e];
        out[(size_t)(e0 + e) * OUTD + o] = s;
    }
}

extern "C" void kernel_launch(void* const* d_in, const int* in_sizes, int n_in,
                              void* d_out, int out_size)
{
    const float* x    = (const float*)d_in[0];
    const float* Wih0 = (const float*)d_in[1];
    const float* Whh0 = (const float*)d_in[2];
    const float* bih0 = (const float*)d_in[3];
    const float* bhh0 = (const float*)d_in[4];
    const float* Wih1 = (const float*)d_in[5];
    const float* Whh1 = (const float*)d_in[6];
    const float* bih1 = (const float*)d_in[7];
    const float* bhh1 = (const float*)d_in[8];
    const float* Wlin = (const float*)d_in[9];
    const float* blin = (const float*)d_in[10];
    float* out = (float*)d_out;

    int B = in_sizes[0] / (TT * IND);   // 16384
    int grid = B / EE;                  // 1024

    cudaFuncSetAttribute(rnn_fused_kernel,
                         cudaFuncAttributeMaxDynamicSharedMemorySize, SMEM_BYTES);
    rnn_fused_kernel<<<grid, NT, SMEM_BYTES>>>(
        x, Wih0, Whh0, bih0, bhh0, Wih1, Whh1, bih1, bhh1, Wlin, blin, out);
}